// round 11
// baseline (speedup 1.0000x reference)
#include <cuda_runtime.h>
#include <cuda_bf16.h>
#include <math.h>

#define BB 2
#define CC 256
#define H2 128
#define W2 128
#define NWIN 512
#define NPOS 64
#define NHEADS 8
#define HD 32
#define ATT_SCALE 0.17677669529663687f
#define APAD 68

typedef unsigned long long ull;

__device__ __forceinline__ ull pack2(float lo, float hi) {
    ull r; asm("mov.b64 %0, {%1,%2};" : "=l"(r) : "f"(lo), "f"(hi)); return r;
}
__device__ __forceinline__ void fma2(ull& d, ull a, ull b) {
    asm("fma.rn.f32x2 %0, %1, %2, %0;" : "+l"(d) : "l"(a), "l"(b));
}
__device__ __forceinline__ float2 unpack2(ull v) {
    float2 f; asm("mov.b64 {%0,%1}, %2;" : "=f"(f.x), "=f"(f.y) : "l"(v)); return f;
}

// Scratch in window layout: [win][ch][p]
__device__ float g_llw  [NWIN * CC * NPOS];
__device__ float g_lhw  [NWIN * CC * NPOS];
__device__ float g_hlw  [NWIN * CC * NPOS];
__device__ float g_hhw  [NWIN * CC * NPOS];
__device__ float g_relu [NWIN * CC * NPOS];
__device__ float g_llout[NWIN * CC * NPOS];

// ---------------------------------------------------------------------------
// Kernel A: forward wavelet, 4 pixels per thread
// ---------------------------------------------------------------------------
__global__ void wt_kernel(const float* __restrict__ x, const float* __restrict__ wf) {
    int idx = blockIdx.x * blockDim.x + threadIdx.x;   // total/4 threads
    int xq = idx & 31;                 // xx/4
    int y  = (idx >> 5) & 127;
    int ch = (idx >> 12) & 255;
    int b  = idx >> 20;
    int xx = xq << 2;

    const float* px = x + (((size_t)(b * CC + ch) * 256 + 2 * y) * 256 + 2 * xx);
    float4 r0a = *(const float4*)px;
    float4 r0b = *(const float4*)(px + 4);
    float4 r1a = *(const float4*)(px + 256);
    float4 r1b = *(const float4*)(px + 260);

    float t[4], u[4], s[4], v[4];
    t[0]=r0a.x; u[0]=r0a.y; s[0]=r1a.x; v[0]=r1a.y;
    t[1]=r0a.z; u[1]=r0a.w; s[1]=r1a.z; v[1]=r1a.w;
    t[2]=r0b.x; u[2]=r0b.y; s[2]=r1b.x; v[2]=r1b.y;
    t[3]=r0b.z; u[3]=r0b.w; s[3]=r1b.z; v[3]=r1b.w;

    int win = b * 256 + (y >> 3) * 16 + (xx >> 3);
    int off = (win * CC + ch) * NPOS + (y & 7) * 8 + (xx & 7);
    const float* w = wf + ch * 16;

    float4 ll, lh, hl, hh;
    float* pll = (float*)&ll; float* plh = (float*)&lh;
    float* phl = (float*)&hl; float* phh = (float*)&hh;
    #pragma unroll
    for (int j = 0; j < 4; ++j) {
        pll[j] = w[0]*t[j]  + w[1]*u[j]  + w[2]*s[j]  + w[3]*v[j];
        plh[j] = w[4]*t[j]  + w[5]*u[j]  + w[6]*s[j]  + w[7]*v[j];
        phl[j] = w[8]*t[j]  + w[9]*u[j]  + w[10]*s[j] + w[11]*v[j];
        phh[j] = w[12]*t[j] + w[13]*u[j] + w[14]*s[j] + w[15]*v[j];
    }
    *(float4*)&g_llw[off] = ll;
    *(float4*)&g_lhw[off] = lh;
    *(float4*)&g_hlw[off] = hl;
    *(float4*)&g_hhw[off] = hh;
}

// ---------------------------------------------------------------------------
// Kernel B: per-window cascaded head attention (+relu), software-pipelined
// ---------------------------------------------------------------------------
__global__ void __launch_bounds__(256, 3) attn_kernel(const float* __restrict__ dw_w,
                                                      const float* __restrict__ dw_b,
                                                      const float* __restrict__ ab) {
    extern __shared__ float sm[];
    float* s_ab   = sm;                 // 512
    float* s_w    = sm + 512;           // 800
    float* s_lh   = sm + 1312;          // 2048
    float* s_k    = sm + 3360;          // 2048
    float* s_v    = sm + 5408;          // 2048
    float* s_attn = sm + 7456;          // 64*68 = 4352
    ull*   s_qd   = (ull*)(sm + 11808); // 2048 ull

    int win = blockIdx.x;
    int tid = threadIdx.x;

    // ---- pre-loop: stage head-0 tiles + v + bias table ----
    for (int i = tid; i < 512; i += 256) s_ab[i] = ab[i];
    {
        const float4* sl = (const float4*)(g_lhw + (size_t)win * CC * NPOS);
        const float4* sk = (const float4*)(g_hlw + (size_t)win * CC * NPOS);
        const float4* sv = (const float4*)(g_llw + (size_t)win * CC * NPOS);
        float4* dl = (float4*)s_lh; float4* dk = (float4*)s_k; float4* dv = (float4*)s_v;
        #pragma unroll
        for (int k = 0; k < 2; ++k) {
            int i = tid + k * 256;
            dl[i] = sl[i]; dk[i] = sk[i]; dv[i] = sv[i];
        }
        for (int i = tid; i < HD * 25; i += 256) s_w[i] = dw_w[i];
    }
    __syncthreads();

    const int cd  = tid >> 3;          // conv d
    const int cix = tid & 7;           // conv ix
    const int tn  = (tid >> 4) << 2;   // QK 4n x 4m tile
    const int tm  = (tid & 15) << 2;
    const int ad0 = (tid >> 4) << 2;   // AV (tid<128): 4d x 4n
    const int an0 = (tid & 15) << 2;
    // f4-index base for the v-update prefetch: consumption set of this thread
    const int pbase = (tid >> 4) * 64 + (tid & 15);

    for (int h = 0; h < NHEADS; ++h) {
        // ---- prefetch next head into registers ----
        float4 p_ll[4];                         // tid<128: llw slice h+1 (v update)
        float4 p_lh[4], p_hl[4]; float p_w[7];  // tid>=128: tiles h+1
        if (h < NHEADS - 1) {
            if (tid < 128) {
                const float4* src = (const float4*)(g_llw + (size_t)(win * CC + (h + 1) * HD) * NPOS);
                #pragma unroll
                for (int k = 0; k < 4; ++k) p_ll[k] = src[pbase + k * 16];
            } else {
                int t = tid - 128;
                const float4* sl = (const float4*)(g_lhw + (size_t)(win * CC + (h + 1) * HD) * NPOS);
                const float4* sk = (const float4*)(g_hlw + (size_t)(win * CC + (h + 1) * HD) * NPOS);
                #pragma unroll
                for (int k = 0; k < 4; ++k) { p_lh[k] = sl[t + k * 128]; p_hl[k] = sk[t + k * 128]; }
                const float* wsrc = dw_w + (h + 1) * HD * 25;
                #pragma unroll
                for (int k = 0; k < 7; ++k) {
                    int i = t + k * 128;
                    p_w[k] = (i < 800) ? wsrc[i] : 0.f;
                }
            }
        }

        // ---- conv: q = dw5x5(lh) + bias, write duplicated pairs ----
        {
            float wv[25];
            #pragma unroll
            for (int t = 0; t < 25; ++t) wv[t] = s_w[cd * 25 + t];
            float bias = dw_b[h * HD + cd];
            #pragma unroll
            for (int iy = 0; iy < 8; ++iy) {
                float acc = bias;
                #pragma unroll
                for (int ky = 0; ky < 5; ++ky) {
                    int yy = iy + ky - 2;
                    if (yy < 0 || yy > 7) continue;
                    #pragma unroll
                    for (int kx = 0; kx < 5; ++kx) {
                        int xc = cix + kx - 2;
                        if (xc >= 0 && xc < 8)
                            acc += wv[ky * 5 + kx] * s_lh[cd * 64 + yy * 8 + xc];
                    }
                }
                s_qd[cd * 64 + iy * 8 + cix] = pack2(acc, acc);
            }
        }
        __syncthreads();

        // ---- QK: 4n x 4m tile, lanes = m-pairs, q pre-duplicated ----
        {
            ull acc0[4] = {}, acc1[4] = {};
            #pragma unroll 8
            for (int d = 0; d < HD; ++d) {
                ulonglong2 k2 = *(const ulonglong2*)&s_k[d * 64 + tm];
                #pragma unroll
                for (int i = 0; i < 4; ++i) {
                    ull q2 = s_qd[d * 64 + tn + i];
                    fma2(acc0[i], q2, k2.x);
                    fma2(acc1[i], q2, k2.y);
                }
            }
            #pragma unroll
            for (int i = 0; i < 4; ++i) {
                int n = tn + i, yn = n >> 3, xn = n & 7;
                float2 pa = unpack2(acc0[i]);
                float2 pb = unpack2(acc1[i]);
                float vals[4] = {pa.x, pa.y, pb.x, pb.y};
                #pragma unroll
                for (int j = 0; j < 4; ++j) {
                    int m = tm + j, ym = m >> 3, xm = m & 7;
                    int bi = abs(yn - ym) * 8 + abs(xn - xm);
                    s_attn[n * APAD + m] = vals[j] * ATT_SCALE + s_ab[h * 64 + bi];
                }
            }
        }
        __syncthreads();

        // ---- softmax: 4 threads/row ----
        {
            int row = tid >> 2, quad = tid & 3;
            float* rp = s_attn + row * APAD + quad * 16;
            float mx = rp[0];
            #pragma unroll
            for (int m = 1; m < 16; ++m) mx = fmaxf(mx, rp[m]);
            mx = fmaxf(mx, __shfl_xor_sync(0xffffffff, mx, 1));
            mx = fmaxf(mx, __shfl_xor_sync(0xffffffff, mx, 2));
            float sum = 0.f, ev[16];
            #pragma unroll
            for (int m = 0; m < 16; ++m) { ev[m] = __expf(rp[m] - mx); sum += ev[m]; }
            sum += __shfl_xor_sync(0xffffffff, sum, 1);
            sum += __shfl_xor_sync(0xffffffff, sum, 2);
            float inv = 1.0f / sum;
            #pragma unroll
            for (int m = 0; m < 16; ++m) rp[m] = ev[m] * inv;
        }
        __syncthreads();

        // ---- AV (tid<128) while tid>=128 stages next head's tiles ----
        ull acc2[4][4];
        if (tid < 128) {
            #pragma unroll
            for (int i = 0; i < 4; ++i)
                #pragma unroll
                for (int j = 0; j < 4; ++j) acc2[i][j] = 0ULL;
            #pragma unroll 4
            for (int mq = 0; mq < 16; ++mq) {
                ulonglong2 vv[4], aa[4];
                #pragma unroll
                for (int i = 0; i < 4; ++i)
                    vv[i] = *(const ulonglong2*)&s_v[(ad0 + i) * 64 + mq * 4];
                #pragma unroll
                for (int j = 0; j < 4; ++j)
                    aa[j] = *(const ulonglong2*)&s_attn[(an0 + j) * APAD + mq * 4];
                #pragma unroll
                for (int i = 0; i < 4; ++i)
                    #pragma unroll
                    for (int j = 0; j < 4; ++j) {
                        fma2(acc2[i][j], vv[i].x, aa[j].x);
                        fma2(acc2[i][j], vv[i].y, aa[j].y);
                    }
            }
        } else if (h < NHEADS - 1) {
            int t = tid - 128;
            float4* dl = (float4*)s_lh; float4* dk = (float4*)s_k;
            #pragma unroll
            for (int k = 0; k < 4; ++k) { dl[t + k * 128] = p_lh[k]; dk[t + k * 128] = p_hl[k]; }
            #pragma unroll
            for (int k = 0; k < 7; ++k) {
                int i = t + k * 128;
                if (i < 800) s_w[i] = p_w[k];
            }
        }
        __syncthreads();

        // ---- writeback relu + v update (tid<128) ----
        if (tid < 128) {
            size_t obase = (size_t)(win * CC + h * HD) * NPOS;
            #pragma unroll
            for (int i = 0; i < 4; ++i) {
                int d = ad0 + i;
                float val[4];
                #pragma unroll
                for (int j = 0; j < 4; ++j) {
                    float2 p = unpack2(acc2[i][j]);
                    val[j] = p.x + p.y;
                }
                *(float4*)&g_relu[obase + d * 64 + an0] =
                    make_float4(fmaxf(val[0], 0.f), fmaxf(val[1], 0.f),
                                fmaxf(val[2], 0.f), fmaxf(val[3], 0.f));
                if (h < NHEADS - 1) {
                    float4 l4 = p_ll[i];   // f4-index pbase + i*16 == d*16 + an0/4
                    *(float4*)&s_v[d * 64 + an0] =
                        make_float4(val[0] + l4.x, val[1] + l4.y,
                                    val[2] + l4.z, val[3] + l4.w);
                }
            }
        }
        __syncthreads();
    }
}

// ---------------------------------------------------------------------------
// Kernel B2: batched proj GEMM, zero-pack (o-pair lanes + pre-duplicated X)
// ---------------------------------------------------------------------------
__global__ void __launch_bounds__(256, 2) proj_kernel(const float* __restrict__ pw,
                                                      const float* __restrict__ pb) {
    extern __shared__ float psm[];
    float* sW  = psm;                    // [cl][o], stride 258
    ull*   sXd = (ull*)(psm + 32 * 258); // [cl][n] duplicated pairs

    int win = blockIdx.x;
    int tid = threadIdx.x;
    int to = (tid >> 3) << 3;
    int tn = (tid & 7) << 3;

    ull acc2[4][8];
    #pragma unroll
    for (int i = 0; i < 4; ++i)
        #pragma unroll
        for (int j = 0; j < 8; ++j) acc2[i][j] = 0ULL;

    for (int c0 = 0; c0 < CC; c0 += 32) {
        for (int i = tid; i < 256 * 32; i += 256) {
            int o = i >> 5, cl = i & 31;
            sW[cl * 258 + o] = pw[o * 256 + c0 + cl];
        }
        {
            const float4* src = (const float4*)(g_relu + (size_t)(win * CC + c0) * NPOS);
            #pragma unroll
            for (int k = 0; k < 2; ++k) {
                int i4 = tid + k * 256;
                float4 v = src[i4];
                ull* d = sXd + i4 * 4;
                d[0] = pack2(v.x, v.x); d[1] = pack2(v.y, v.y);
                d[2] = pack2(v.z, v.z); d[3] = pack2(v.w, v.w);
            }
        }
        __syncthreads();

        #pragma unroll 4
        for (int cl = 0; cl < 32; ++cl) {
            ull w2[4];
            #pragma unroll
            for (int i = 0; i < 4; ++i)
                w2[i] = *(const ull*)&sW[cl * 258 + to + 2 * i];
            const ull* xr = sXd + cl * 64 + tn;
            ull xd[8];
            #pragma unroll
            for (int j = 0; j < 8; ++j) xd[j] = xr[j];
            #pragma unroll
            for (int i = 0; i < 4; ++i)
                #pragma unroll
                for (int j = 0; j < 8; ++j) fma2(acc2[i][j], w2[i], xd[j]);
        }
        __syncthreads();
    }

    #pragma unroll
    for (int i = 0; i < 4; ++i) {
        int o0 = to + 2 * i;
        float b0 = pb[o0], b1 = pb[o0 + 1];
        float r0[8], r1[8];
        #pragma unroll
        for (int j = 0; j < 8; ++j) {
            float2 p = unpack2(acc2[i][j]);
            r0[j] = p.x + b0; r1[j] = p.y + b1;
        }
        float* out0 = g_llout + (size_t)(win * CC + o0) * NPOS + tn;
        float* out1 = out0 + NPOS;
        *(float4*)out0       = make_float4(r0[0], r0[1], r0[2], r0[3]);
        *(float4*)(out0 + 4) = make_float4(r0[4], r0[5], r0[6], r0[7]);
        *(float4*)out1       = make_float4(r1[0], r1[1], r1[2], r1[3]);
        *(float4*)(out1 + 4) = make_float4(r1[4], r1[5], r1[6], r1[7]);
    }
}

// ---------------------------------------------------------------------------
// Kernel C: inverse wavelet, 4 cells per thread
// ---------------------------------------------------------------------------
__global__ void iwt_kernel(const float* __restrict__ iwf, float* __restrict__ out) {
    int idx = blockIdx.x * blockDim.x + threadIdx.x;   // total/4 threads
    int xq = idx & 31;
    int y  = (idx >> 5) & 127;
    int ch = (idx >> 12) & 255;
    int b  = idx >> 20;
    int xx = xq << 2;

    int win = b * 256 + (y >> 3) * 16 + (xx >> 3);
    int off = (win * CC + ch) * NPOS + (y & 7) * 8 + (xx & 7);
    float4 v0 = *(const float4*)&g_llout[off];
    float4 v1 = *(const float4*)&g_lhw[off];
    float4 v2 = *(const float4*)&g_hlw[off];
    float4 v3 = *(const float4*)&g_hhw[off];
    const float* a0 = (const float*)&v0;
    const float* a1 = (const float*)&v1;
    const float* a2 = (const float*)&v2;
    const float* a3 = (const float*)&v3;

    const float* w = iwf + ch * 16;
    float* po = out + (((size_t)(b * CC + ch) * 256 + 2 * y) * 256 + 2 * xx);

    float r0[8], r1[8];
    #pragma unroll
    for (int j = 0; j < 4; ++j) {
        r0[2*j]   = w[0]*a0[j] + w[4]*a1[j] + w[8]*a2[j]  + w[12]*a3[j];
        r0[2*j+1] = w[1]*a0[j] + w[5]*a1[j] + w[9]*a2[j]  + w[13]*a3[j];
        r1[2*j]   = w[2]*a0[j] + w[6]*a1[j] + w[10]*a2[j] + w[14]*a3[j];
        r1[2*j+1] = w[3]*a0[j] + w[7]*a1[j] + w[11]*a2[j] + w[15]*a3[j];
    }
    *(float4*)po         = make_float4(r0[0], r0[1], r0[2], r0[3]);
    *(float4*)(po + 4)   = make_float4(r0[4], r0[5], r0[6], r0[7]);
    *(float4*)(po + 256) = make_float4(r1[0], r1[1], r1[2], r1[3]);
    *(float4*)(po + 260) = make_float4(r1[4], r1[5], r1[6], r1[7]);
}

// ---------------------------------------------------------------------------
extern "C" void kernel_launch(void* const* d_in, const int* in_sizes, int n_in,
                              void* d_out, int out_size) {
    const float* x    = (const float*)d_in[0];
    const float* wtf  = (const float*)d_in[1];
    const float* iwtf = (const float*)d_in[2];
    const float* dww  = (const float*)d_in[3];
    const float* dwb  = (const float*)d_in[4];
    const float* pw   = (const float*)d_in[5];
    const float* pb   = (const float*)d_in[6];
    const float* ab   = (const float*)d_in[7];
    float* out = (float*)d_out;

    int quarter = BB * CC * H2 * W2 / 4;  // 2,097,152
    wt_kernel<<<quarter / 256, 256>>>(x, wtf);

    size_t asmem = 15904 * sizeof(float);   // 63616 B
    cudaFuncSetAttribute(attn_kernel, cudaFuncAttributeMaxDynamicSharedMemorySize, (int)asmem);
    attn_kernel<<<NWIN, 256, asmem>>>(dww, dwb, ab);

    size_t psmem = (32 * 258) * sizeof(float) + (32 * 64) * sizeof(ull);  // 49408 B
    cudaFuncSetAttribute(proj_kernel, cudaFuncAttributeMaxDynamicSharedMemorySize, (int)psmem);
    proj_kernel<<<NWIN, 256, psmem>>>(pw, pb);

    iwt_kernel<<<quarter / 256, 256>>>(iwtf, out);
}

// round 13
// speedup vs baseline: 1.8214x; 1.8214x over previous
#include <cuda_runtime.h>
#include <cuda_bf16.h>
#include <math.h>

#define BB 2
#define CC 256
#define H2 128
#define W2 128
#define NWIN 512
#define NPOS 64
#define NHEADS 8
#define HD 32
#define ATT_SCALE 0.17677669529663687f
#define APAD 68     // attn row stride: 68 ≡ 4 (mod 8) -> conflict-free strided LDS.128
#define LHP 72      // lh/q row stride: 72 ≡ 8 (mod 32) -> conv conflict-free

typedef unsigned long long ull;
typedef unsigned int u32;

__device__ __forceinline__ ull pack2(float lo, float hi) {
    ull r; asm("mov.b64 %0, {%1,%2};" : "=l"(r) : "f"(lo), "f"(hi)); return r;
}
__device__ __forceinline__ void fma2(ull& d, ull a, ull b) {
    asm("fma.rn.f32x2 %0, %1, %2, %0;" : "+l"(d) : "l"(a), "l"(b));
}
__device__ __forceinline__ float2 unpack2(ull v) {
    float2 f; asm("mov.b64 {%0,%1}, %2;" : "=f"(f.x), "=f"(f.y) : "l"(v)); return f;
}
__device__ __forceinline__ void cpa16(u32 dst, const void* src) {
    asm volatile("cp.async.cg.shared.global [%0], [%1], 16;" :: "r"(dst), "l"(src));
}
#define CP_COMMIT() asm volatile("cp.async.commit_group;")
#define CP_WAIT(n)  asm volatile("cp.async.wait_group %0;" :: "n"(n))

// Scratch in window layout: [win][ch][p]
__device__ float g_llw  [NWIN * CC * NPOS];
__device__ float g_lhw  [NWIN * CC * NPOS];
__device__ float g_hlw  [NWIN * CC * NPOS];
__device__ float g_hhw  [NWIN * CC * NPOS];
__device__ float g_relu [NWIN * CC * NPOS];
__device__ float g_llout[NWIN * CC * NPOS];

// ---------------------------------------------------------------------------
// Kernel A: forward wavelet, 2 pixels per thread (R8-benched best)
// ---------------------------------------------------------------------------
__global__ void wt_kernel(const float* __restrict__ x, const float* __restrict__ wf) {
    int idx = blockIdx.x * blockDim.x + threadIdx.x;
    int xp = idx & 63;
    int y  = (idx >> 6) & 127;
    int ch = (idx >> 13) & 255;
    int b  = idx >> 21;
    int xx = xp << 1;

    const float* px = x + (((size_t)(b * CC + ch) * 256 + 2 * y) * 256 + 2 * xx);
    float4 r0 = *(const float4*)px;
    float4 r1 = *(const float4*)(px + 256);

    int win = b * 256 + (y >> 3) * 16 + (xx >> 3);
    int off = (win * CC + ch) * NPOS + (y & 7) * 8 + (xx & 7);
    const float* w = wf + ch * 16;

    float2 ll, lh, hl, hh;
    ll.x = w[0]*r0.x + w[1]*r0.y + w[2]*r1.x + w[3]*r1.y;
    ll.y = w[0]*r0.z + w[1]*r0.w + w[2]*r1.z + w[3]*r1.w;
    lh.x = w[4]*r0.x + w[5]*r0.y + w[6]*r1.x + w[7]*r1.y;
    lh.y = w[4]*r0.z + w[5]*r0.w + w[6]*r1.z + w[7]*r1.w;
    hl.x = w[8]*r0.x + w[9]*r0.y + w[10]*r1.x + w[11]*r1.y;
    hl.y = w[8]*r0.z + w[9]*r0.w + w[10]*r1.z + w[11]*r1.w;
    hh.x = w[12]*r0.x + w[13]*r0.y + w[14]*r1.x + w[15]*r1.y;
    hh.y = w[12]*r0.z + w[13]*r0.w + w[14]*r1.z + w[15]*r1.w;

    *(float2*)&g_llw[off] = ll;
    *(float2*)&g_lhw[off] = lh;
    *(float2*)&g_hlw[off] = hl;
    *(float2*)&g_hhw[off] = hh;
}

// ---------------------------------------------------------------------------
// Kernel B: cascaded head attention, cp.async pipelined, conflict-free smem
// floats: ab 512 | w 800 | lh 2304(72-str) | k 2048 | v 2048 | q 2304 | attn 4352
// total 14368 floats = 57472 B
// ---------------------------------------------------------------------------
__global__ void __launch_bounds__(256) attn_kernel(const float* __restrict__ dw_w,
                                                   const float* __restrict__ dw_b,
                                                   const float* __restrict__ ab) {
    extern __shared__ float sm[];
    float* s_ab   = sm;            // 512
    float* s_w    = sm + 512;      // 800
    float* s_lh   = sm + 1312;     // 32 x 72
    float* s_k    = sm + 3616;     // 32 x 64
    float* s_v    = sm + 5664;     // 32 x 64
    float* s_q    = sm + 7712;     // 32 x 72
    float* s_attn = sm + 10016;    // 64 x 68

    const int win = blockIdx.x;
    const int tid = threadIdx.x;
    const size_t wbase = (size_t)win * CC * NPOS;

    const u32 u_lh = (u32)__cvta_generic_to_shared(s_lh);
    const u32 u_w  = (u32)__cvta_generic_to_shared(s_w);
    const u32 u_k  = (u32)__cvta_generic_to_shared(s_k);

    // ---- prologue: bias table + v(head0) normal; lh/w and k via cp.async ----
    for (int i = tid; i < 512; i += 256) s_ab[i] = ab[i];
    {
        const float4* sv = (const float4*)(g_llw + wbase);
        float4* dv = (float4*)s_v;
        dv[tid] = sv[tid]; dv[tid + 256] = sv[tid + 256];
    }
    {   // Group1(0): lh (padded rows) + w
        const float4* src = (const float4*)(g_lhw + wbase);
        #pragma unroll
        for (int kk = 0; kk < 2; ++kk) {
            int i = tid + kk * 256;
            int d = i >> 4, c = i & 15;
            cpa16(u_lh + (u32)(d * (LHP / 4) + c) * 16, src + i);
        }
        if (tid < 200) cpa16(u_w + tid * 16, (const float4*)dw_w + tid);
        CP_COMMIT();
    }
    {   // Group2(0): k
        const float4* src = (const float4*)(g_hlw + wbase);
        cpa16(u_k + tid * 16, src + tid);
        cpa16(u_k + (tid + 256) * 16, src + tid + 256);
        CP_COMMIT();
    }

    const int cd  = tid >> 3;          // conv d
    const int cix = tid & 7;           // conv ix
    const int tn  = (tid >> 4) << 2;   // QK: 4 rows n
    const int tm  = (tid & 15) << 2;   // QK: 4 cols m
    const int ad0 = (tid >> 4) << 1;   // AV: 2 d's
    const int ln  = tid & 15;          // AV: n = ln + 16j

    float vnew[2][4];                  // deferred v-update values

    for (int h = 0; h < NHEADS; ++h) {
        CP_WAIT(1);                    // Group1(h) complete
        __syncthreads();

        // deferred v-update from head h-1 (safe: previous AV readers done)
        if (h > 0) {
            #pragma unroll
            for (int i = 0; i < 2; ++i)
                #pragma unroll
                for (int j = 0; j < 4; ++j)
                    s_v[(ad0 + i) * 64 + ln + 16 * j] = vnew[i][j];
        }

        // ---- conv: q = dw5x5(lh) + bias (conflict-free, stride-72 rows) ----
        {
            float wv[25];
            #pragma unroll
            for (int t = 0; t < 25; ++t) wv[t] = s_w[cd * 25 + t];
            float bias = __ldg(&dw_b[h * HD + cd]);
            #pragma unroll
            for (int iy = 0; iy < 8; ++iy) {
                float acc = bias;
                #pragma unroll
                for (int ky = 0; ky < 5; ++ky) {
                    int yy = iy + ky - 2;
                    if (yy < 0 || yy > 7) continue;
                    #pragma unroll
                    for (int kx = 0; kx < 5; ++kx) {
                        int xc = cix + kx - 2;
                        if (xc >= 0 && xc < 8)
                            acc += wv[ky * 5 + kx] * s_lh[cd * LHP + yy * 8 + xc];
                    }
                }
                s_q[cd * LHP + iy * 8 + cix] = acc;
            }
        }
        CP_WAIT(0);                    // Group2(h) complete
        __syncthreads();

        // prefetch Group1(h+1): lh + w (buffers free: conv done)
        if (h < NHEADS - 1) {
            const float4* src = (const float4*)(g_lhw + wbase + (size_t)(h + 1) * HD * NPOS);
            #pragma unroll
            for (int kk = 0; kk < 2; ++kk) {
                int i = tid + kk * 256;
                int d = i >> 4, c = i & 15;
                cpa16(u_lh + (u32)(d * (LHP / 4) + c) * 16, src + i);
            }
            if (tid < 200) cpa16(u_w + tid * 16, (const float4*)(dw_w + (h + 1) * HD * 25) + tid);
            CP_COMMIT();
        }

        // ---- QK + in-register softmax ----
        {
            ull a0[4] = {}, a1[4] = {};
            #pragma unroll 8
            for (int d = 0; d < HD; ++d) {
                ulonglong2 k2 = *(const ulonglong2*)&s_k[d * 64 + tm];
                float4 q4 = *(const float4*)&s_q[d * LHP + tn];
                ull qp[4] = {pack2(q4.x, q4.x), pack2(q4.y, q4.y),
                             pack2(q4.z, q4.z), pack2(q4.w, q4.w)};
                #pragma unroll
                for (int i = 0; i < 4; ++i) { fma2(a0[i], qp[i], k2.x); fma2(a1[i], qp[i], k2.y); }
            }
            float vals[4][4];
            #pragma unroll
            for (int i = 0; i < 4; ++i) {
                int n = tn + i, yn = n >> 3, xn = n & 7;
                float2 pa = unpack2(a0[i]);
                float2 pb = unpack2(a1[i]);
                float raw[4] = {pa.x, pa.y, pb.x, pb.y};
                #pragma unroll
                for (int j = 0; j < 4; ++j) {
                    int m = tm + j, ym = m >> 3, xm = m & 7;
                    int bi = abs(yn - ym) * 8 + abs(xn - xm);
                    vals[i][j] = raw[j] * ATT_SCALE + s_ab[h * 64 + bi];
                }
            }
            // softmax across the 16-lane group holding each row
            #pragma unroll
            for (int i = 0; i < 4; ++i) {
                float mx = fmaxf(fmaxf(vals[i][0], vals[i][1]), fmaxf(vals[i][2], vals[i][3]));
                mx = fmaxf(mx, __shfl_xor_sync(0xffffffff, mx, 1));
                mx = fmaxf(mx, __shfl_xor_sync(0xffffffff, mx, 2));
                mx = fmaxf(mx, __shfl_xor_sync(0xffffffff, mx, 4));
                mx = fmaxf(mx, __shfl_xor_sync(0xffffffff, mx, 8));
                float e0 = __expf(vals[i][0] - mx), e1 = __expf(vals[i][1] - mx);
                float e2 = __expf(vals[i][2] - mx), e3 = __expf(vals[i][3] - mx);
                float sum = e0 + e1 + e2 + e3;
                sum += __shfl_xor_sync(0xffffffff, sum, 1);
                sum += __shfl_xor_sync(0xffffffff, sum, 2);
                sum += __shfl_xor_sync(0xffffffff, sum, 4);
                sum += __shfl_xor_sync(0xffffffff, sum, 8);
                float inv = 1.0f / sum;
                *(ull*)&s_attn[(tn + i) * APAD + tm]     = pack2(e0 * inv, e1 * inv);
                *(ull*)&s_attn[(tn + i) * APAD + tm + 2] = pack2(e2 * inv, e3 * inv);
            }
        }
        __syncthreads();

        // prefetch Group2(h+1): k (buffer free: QK done)
        if (h < NHEADS - 1) {
            const float4* src = (const float4*)(g_hlw + wbase + (size_t)(h + 1) * HD * NPOS);
            cpa16(u_k + tid * 16, src + tid);
            cpa16(u_k + (tid + 256) * 16, src + tid + 256);
            CP_COMMIT();
        }

        // ---- AV: all 256 threads, 2d x 4n (strided n -> conflict-free) ----
        float pll[2][4];
        if (h < NHEADS - 1) {
            const float* src = g_llw + wbase + (size_t)(h + 1) * HD * NPOS;
            #pragma unroll
            for (int i = 0; i < 2; ++i)
                #pragma unroll
                for (int j = 0; j < 4; ++j)
                    pll[i][j] = __ldg(&src[(ad0 + i) * 64 + ln + 16 * j]);
        }
        ull acc2[2][4];
        #pragma unroll
        for (int i = 0; i < 2; ++i)
            #pragma unroll
            for (int j = 0; j < 4; ++j) acc2[i][j] = 0ULL;
        #pragma unroll 4
        for (int mq = 0; mq < 16; ++mq) {
            ulonglong2 vv0 = *(const ulonglong2*)&s_v[ad0 * 64 + mq * 4];
            ulonglong2 vv1 = *(const ulonglong2*)&s_v[(ad0 + 1) * 64 + mq * 4];
            ulonglong2 aa[4];
            #pragma unroll
            for (int j = 0; j < 4; ++j)
                aa[j] = *(const ulonglong2*)&s_attn[(ln + 16 * j) * APAD + mq * 4];
            #pragma unroll
            for (int j = 0; j < 4; ++j) {
                fma2(acc2[0][j], vv0.x, aa[j].x); fma2(acc2[0][j], vv0.y, aa[j].y);
                fma2(acc2[1][j], vv1.x, aa[j].x); fma2(acc2[1][j], vv1.y, aa[j].y);
            }
        }
        // relu writeback now; v-update deferred to next head top
        {
            size_t ob = wbase + (size_t)h * HD * NPOS;
            #pragma unroll
            for (int i = 0; i < 2; ++i) {
                int d = ad0 + i;
                #pragma unroll
                for (int j = 0; j < 4; ++j) {
                    float2 p = unpack2(acc2[i][j]);
                    float val = p.x + p.y;
                    g_relu[ob + d * 64 + ln + 16 * j] = fmaxf(val, 0.f);
                    if (h < NHEADS - 1) vnew[i][j] = val + pll[i][j];
                }
            }
        }
    }
}

// ---------------------------------------------------------------------------
// Kernel B2: batched proj GEMM, zero-pack o-pairs, conflict-free X reads
// smem: sW 32*258 floats + sXd 2048 ull = 49408 B
// ---------------------------------------------------------------------------
__global__ void __launch_bounds__(256) proj_kernel(const float* __restrict__ pw,
                                                   const float* __restrict__ pb) {
    extern __shared__ float psm[];
    float* sW  = psm;                       // [cl][o], stride 258
    ull*   sXd = (ull*)(psm + 32 * 258);    // [cl][n] duplicated pairs

    int win = blockIdx.x;
    int tid = threadIdx.x;
    int to  = (tid >> 3) << 3;              // 8 o's = 4 o-pairs
    int lnn = tid & 7;                      // n = lnn + 8j

    ull acc2[4][8];
    #pragma unroll
    for (int i = 0; i < 4; ++i)
        #pragma unroll
        for (int j = 0; j < 8; ++j) acc2[i][j] = 0ULL;

    for (int c0 = 0; c0 < CC; c0 += 32) {
        for (int i = tid; i < 256 * 32; i += 256) {
            int o = i >> 5, cl = i & 31;
            sW[cl * 258 + o] = pw[o * 256 + c0 + cl];
        }
        {
            const float* xs = g_relu + (size_t)(win * CC + c0) * NPOS;
            #pragma unroll
            for (int k = 0; k < 8; ++k) {
                int j = tid + k * 256;
                float v = xs[j];
                sXd[j] = pack2(v, v);
            }
        }
        __syncthreads();

        #pragma unroll 2
        for (int cl = 0; cl < 32; ++cl) {
            ull w2[4];
            #pragma unroll
            for (int i = 0; i < 4; ++i)
                w2[i] = *(const ull*)&sW[cl * 258 + to + 2 * i];
            ull xd[8];
            #pragma unroll
            for (int j = 0; j < 8; ++j) xd[j] = sXd[cl * 64 + lnn + 8 * j];
            #pragma unroll
            for (int i = 0; i < 4; ++i)
                #pragma unroll
                for (int j = 0; j < 8; ++j) fma2(acc2[i][j], w2[i], xd[j]);
        }
        __syncthreads();
    }

    #pragma unroll
    for (int i = 0; i < 4; ++i) {
        int o0 = to + 2 * i;
        float b0 = pb[o0], b1 = pb[o0 + 1];
        float* out0 = g_llout + (size_t)(win * CC + o0) * NPOS;
        float* out1 = out0 + NPOS;
        #pragma unroll
        for (int j = 0; j < 8; ++j) {
            float2 p = unpack2(acc2[i][j]);
            int n = lnn + 8 * j;
            out0[n] = p.x + b0;
            out1[n] = p.y + b1;
        }
    }
}

// ---------------------------------------------------------------------------
// Kernel C: inverse wavelet, 2 cells per thread (R8-benched best)
// ---------------------------------------------------------------------------
__global__ void iwt_kernel(const float* __restrict__ iwf, float* __restrict__ out) {
    int idx = blockIdx.x * blockDim.x + threadIdx.x;
    int xp = idx & 63;
    int y  = (idx >> 6) & 127;
    int ch = (idx >> 13) & 255;
    int b  = idx >> 21;
    int xx = xp << 1;

    int win = b * 256 + (y >> 3) * 16 + (xx >> 3);
    int off = (win * CC + ch) * NPOS + (y & 7) * 8 + (xx & 7);
    float2 v0 = *(const float2*)&g_llout[off];
    float2 v1 = *(const float2*)&g_lhw[off];
    float2 v2 = *(const float2*)&g_hlw[off];
    float2 v3 = *(const float2*)&g_hhw[off];

    const float* w = iwf + ch * 16;
    float* po = out + (((size_t)(b * CC + ch) * 256 + 2 * y) * 256 + 2 * xx);

    float4 r0, r1;
    r0.x = w[0]*v0.x + w[4]*v1.x + w[8]*v2.x  + w[12]*v3.x;
    r0.y = w[1]*v0.x + w[5]*v1.x + w[9]*v2.x  + w[13]*v3.x;
    r0.z = w[0]*v0.y + w[4]*v1.y + w[8]*v2.y  + w[12]*v3.y;
    r0.w = w[1]*v0.y + w[5]*v1.y + w[9]*v2.y  + w[13]*v3.y;
    r1.x = w[2]*v0.x + w[6]*v1.x + w[10]*v2.x + w[14]*v3.x;
    r1.y = w[3]*v0.x + w[7]*v1.x + w[11]*v2.x + w[15]*v3.x;
    r1.z = w[2]*v0.y + w[6]*v1.y + w[10]*v2.y + w[14]*v3.y;
    r1.w = w[3]*v0.y + w[7]*v1.y + w[11]*v2.y + w[15]*v3.y;

    *(float4*)po         = r0;
    *(float4*)(po + 256) = r1;
}

// ---------------------------------------------------------------------------
extern "C" void kernel_launch(void* const* d_in, const int* in_sizes, int n_in,
                              void* d_out, int out_size) {
    const float* x    = (const float*)d_in[0];
    const float* wtf  = (const float*)d_in[1];
    const float* iwtf = (const float*)d_in[2];
    const float* dww  = (const float*)d_in[3];
    const float* dwb  = (const float*)d_in[4];
    const float* pw   = (const float*)d_in[5];
    const float* pb   = (const float*)d_in[6];
    const float* ab   = (const float*)d_in[7];
    float* out = (float*)d_out;

    int half = BB * CC * H2 * W2 / 2;  // 4,194,304
    wt_kernel<<<half / 256, 256>>>(x, wtf);

    size_t asmem = 14368 * sizeof(float);   // 57472 B
    cudaFuncSetAttribute(attn_kernel, cudaFuncAttributeMaxDynamicSharedMemorySize, (int)asmem);
    attn_kernel<<<NWIN, 256, asmem>>>(dww, dwb, ab);

    size_t psmem = (32 * 258) * sizeof(float) + 2048 * sizeof(ull);  // 49408 B
    cudaFuncSetAttribute(proj_kernel, cudaFuncAttributeMaxDynamicSharedMemorySize, (int)psmem);
    proj_kernel<<<NWIN, 256, psmem>>>(pw, pb);

    iwt_kernel<<<half / 256, 256>>>(iwtf, out);
}

// round 14
// speedup vs baseline: 1.9076x; 1.0473x over previous
#include <cuda_runtime.h>
#include <cuda_bf16.h>
#include <math.h>

#define BB 2
#define CC 256
#define H2 128
#define W2 128
#define NWIN 512
#define NPOS 64
#define NHEADS 8
#define HD 32
#define ATT_SCALE 0.17677669529663687f
#define APAD 68     // probs row stride in smem (strided-n AV reads conflict-free)
#define LHP 72      // lh/q row stride: 72 ≡ 8 (mod 32) -> conv conflict-free

typedef unsigned long long ull;
typedef unsigned int u32;

__device__ __forceinline__ ull pack2(float lo, float hi) {
    ull r; asm("mov.b64 %0, {%1,%2};" : "=l"(r) : "f"(lo), "f"(hi)); return r;
}
__device__ __forceinline__ void fma2(ull& d, ull a, ull b) {
    asm("fma.rn.f32x2 %0, %1, %2, %0;" : "+l"(d) : "l"(a), "l"(b));
}
__device__ __forceinline__ float2 unpack2(ull v) {
    float2 f; asm("mov.b64 {%0,%1}, %2;" : "=f"(f.x), "=f"(f.y) : "l"(v)); return f;
}
__device__ __forceinline__ void cpa16(u32 dst, const void* src) {
    asm volatile("cp.async.cg.shared.global [%0], [%1], 16;" :: "r"(dst), "l"(src));
}
#define CP_COMMIT() asm volatile("cp.async.commit_group;")
#define CP_WAIT(n)  asm volatile("cp.async.wait_group %0;" :: "n"(n))

// Scratch in window layout: [win][ch][p]
__device__ float g_llw  [NWIN * CC * NPOS];
__device__ float g_lhw  [NWIN * CC * NPOS];
__device__ float g_hlw  [NWIN * CC * NPOS];
__device__ float g_hhw  [NWIN * CC * NPOS];
__device__ float g_relu [NWIN * CC * NPOS];
__device__ float g_llout[NWIN * CC * NPOS];
// softmaxed attention probabilities: [win*8+h][n][m]
__device__ float g_attn [NWIN * NHEADS * NPOS * NPOS];

// ---------------------------------------------------------------------------
// Kernel A: forward wavelet, 2 pixels per thread
// ---------------------------------------------------------------------------
__global__ void wt_kernel(const float* __restrict__ x, const float* __restrict__ wf) {
    int idx = blockIdx.x * blockDim.x + threadIdx.x;
    int xp = idx & 63;
    int y  = (idx >> 6) & 127;
    int ch = (idx >> 13) & 255;
    int b  = idx >> 21;
    int xx = xp << 1;

    const float* px = x + (((size_t)(b * CC + ch) * 256 + 2 * y) * 256 + 2 * xx);
    float4 r0 = *(const float4*)px;
    float4 r1 = *(const float4*)(px + 256);

    int win = b * 256 + (y >> 3) * 16 + (xx >> 3);
    int off = (win * CC + ch) * NPOS + (y & 7) * 8 + (xx & 7);
    const float* w = wf + ch * 16;

    float2 ll, lh, hl, hh;
    ll.x = w[0]*r0.x + w[1]*r0.y + w[2]*r1.x + w[3]*r1.y;
    ll.y = w[0]*r0.z + w[1]*r0.w + w[2]*r1.z + w[3]*r1.w;
    lh.x = w[4]*r0.x + w[5]*r0.y + w[6]*r1.x + w[7]*r1.y;
    lh.y = w[4]*r0.z + w[5]*r0.w + w[6]*r1.z + w[7]*r1.w;
    hl.x = w[8]*r0.x + w[9]*r0.y + w[10]*r1.x + w[11]*r1.y;
    hl.y = w[8]*r0.z + w[9]*r0.w + w[10]*r1.z + w[11]*r1.w;
    hh.x = w[12]*r0.x + w[13]*r0.y + w[14]*r1.x + w[15]*r1.y;
    hh.y = w[12]*r0.z + w[13]*r0.w + w[14]*r1.z + w[15]*r1.w;

    *(float2*)&g_llw[off] = ll;
    *(float2*)&g_lhw[off] = lh;
    *(float2*)&g_hlw[off] = hl;
    *(float2*)&g_hhw[off] = hh;
}

// ---------------------------------------------------------------------------
// Kernel B1: per-(window, head) conv + QK + softmax -> g_attn. Fully parallel.
// smem floats: w 800 | lh 2296(stride 72) | k 2048 | q 2296 | abr 64 = 7504
// ---------------------------------------------------------------------------
__global__ void __launch_bounds__(256) qk_kernel(const float* __restrict__ dw_w,
                                                 const float* __restrict__ dw_b,
                                                 const float* __restrict__ ab) {
    extern __shared__ float sm[];
    float* s_w   = sm;          // 800
    float* s_lh  = sm + 800;    // 2296
    float* s_k   = sm + 3096;   // 2048
    float* s_q   = sm + 5144;   // 2296
    float* s_abr = sm + 7440;   // 64

    const int bid = blockIdx.x;
    const int win = bid >> 3, h = bid & 7;
    const int tid = threadIdx.x;
    const size_t hs = ((size_t)win * CC + h * HD) * NPOS;

    const u32 u_lh = (u32)__cvta_generic_to_shared(s_lh);
    const u32 u_w  = (u32)__cvta_generic_to_shared(s_w);
    const u32 u_k  = (u32)__cvta_generic_to_shared(s_k);

    {   // Group1: lh (padded rows) + conv weights
        const float4* src = (const float4*)(g_lhw + hs);
        #pragma unroll
        for (int kk = 0; kk < 2; ++kk) {
            int i = tid + kk * 256;
            int d = i >> 4, c = i & 15;
            cpa16(u_lh + (u32)(d * 18 + c) * 16, src + i);
        }
        if (tid < 200) cpa16(u_w + tid * 16, (const float4*)(dw_w + h * HD * 25) + tid);
        CP_COMMIT();
    }
    {   // Group2: k
        const float4* src = (const float4*)(g_hlw + hs);
        cpa16(u_k + tid * 16, src + tid);
        cpa16(u_k + (tid + 256) * 16, src + tid + 256);
        CP_COMMIT();
    }
    if (tid < 64) s_abr[tid] = ab[h * 64 + tid];

    const int cd  = tid >> 3;
    const int cix = tid & 7;
    const int tn  = (tid >> 4) << 2;
    const int tm  = (tid & 15) << 2;

    CP_WAIT(1);
    __syncthreads();

    // conv: q = dw5x5(lh) + bias
    {
        float wv[25];
        #pragma unroll
        for (int t = 0; t < 25; ++t) wv[t] = s_w[cd * 25 + t];
        float bias = __ldg(&dw_b[h * HD + cd]);
        #pragma unroll
        for (int iy = 0; iy < 8; ++iy) {
            float acc = bias;
            #pragma unroll
            for (int ky = 0; ky < 5; ++ky) {
                int yy = iy + ky - 2;
                if (yy < 0 || yy > 7) continue;
                #pragma unroll
                for (int kx = 0; kx < 5; ++kx) {
                    int xc = cix + kx - 2;
                    if (xc >= 0 && xc < 8)
                        acc += wv[ky * 5 + kx] * s_lh[cd * LHP + yy * 8 + xc];
                }
            }
            s_q[cd * LHP + iy * 8 + cix] = acc;
        }
    }
    CP_WAIT(0);
    __syncthreads();

    // QK + in-register softmax -> g_attn
    {
        ull a0[4] = {}, a1[4] = {};
        #pragma unroll 8
        for (int d = 0; d < HD; ++d) {
            ulonglong2 k2 = *(const ulonglong2*)&s_k[d * 64 + tm];
            float4 q4 = *(const float4*)&s_q[d * LHP + tn];
            ull qp[4] = {pack2(q4.x, q4.x), pack2(q4.y, q4.y),
                         pack2(q4.z, q4.z), pack2(q4.w, q4.w)};
            #pragma unroll
            for (int i = 0; i < 4; ++i) { fma2(a0[i], qp[i], k2.x); fma2(a1[i], qp[i], k2.y); }
        }
        float* pout = g_attn + (size_t)bid * (NPOS * NPOS);
        #pragma unroll
        for (int i = 0; i < 4; ++i) {
            int n = tn + i, yn = n >> 3, xn = n & 7;
            float2 pa = unpack2(a0[i]);
            float2 pb = unpack2(a1[i]);
            float raw[4] = {pa.x, pa.y, pb.x, pb.y};
            float vals[4];
            #pragma unroll
            for (int j = 0; j < 4; ++j) {
                int m = tm + j, ym = m >> 3, xm = m & 7;
                vals[j] = raw[j] * ATT_SCALE + s_abr[abs(yn - ym) * 8 + abs(xn - xm)];
            }
            float mx = fmaxf(fmaxf(vals[0], vals[1]), fmaxf(vals[2], vals[3]));
            mx = fmaxf(mx, __shfl_xor_sync(0xffffffff, mx, 1));
            mx = fmaxf(mx, __shfl_xor_sync(0xffffffff, mx, 2));
            mx = fmaxf(mx, __shfl_xor_sync(0xffffffff, mx, 4));
            mx = fmaxf(mx, __shfl_xor_sync(0xffffffff, mx, 8));
            float e0 = __expf(vals[0] - mx), e1 = __expf(vals[1] - mx);
            float e2 = __expf(vals[2] - mx), e3 = __expf(vals[3] - mx);
            float sum = e0 + e1 + e2 + e3;
            sum += __shfl_xor_sync(0xffffffff, sum, 1);
            sum += __shfl_xor_sync(0xffffffff, sum, 2);
            sum += __shfl_xor_sync(0xffffffff, sum, 4);
            sum += __shfl_xor_sync(0xffffffff, sum, 8);
            float inv = 1.0f / sum;
            *(float4*)&pout[n * 64 + tm] = make_float4(e0 * inv, e1 * inv, e2 * inv, e3 * inv);
        }
    }
}

// ---------------------------------------------------------------------------
// Kernel B2: serial AV cascade per window; probs double-buffered via cp.async
// smem floats: v 2048 | probs 2 x (64*68) = 8704  -> 10752 floats = 43008 B
// ---------------------------------------------------------------------------
__global__ void __launch_bounds__(256) av_kernel() {
    extern __shared__ float sm[];
    float* s_v  = sm;          // 2048
    float* bufs = sm + 2048;   // 2 x 4352

    const int win = blockIdx.x;
    const int tid = threadIdx.x;
    const size_t wbase = (size_t)win * CC * NPOS;
    const u32 u_buf = (u32)__cvta_generic_to_shared(bufs);

    const int ad0 = (tid >> 4) << 1;   // 2 d's per thread
    const int ln  = tid & 15;          // n = ln + 16j

    {   // v(head0)
        const float4* sv = (const float4*)(g_llw + wbase);
        float4* dv = (float4*)s_v;
        dv[tid] = sv[tid]; dv[tid + 256] = sv[tid + 256];
    }
    // prefetch probs for heads 0 and 1
    #pragma unroll
    for (int g = 0; g < 2; ++g) {
        const float4* src = (const float4*)(g_attn + (size_t)(win * NHEADS + g) * (NPOS * NPOS));
        u32 dst = u_buf + (u32)(g * 4352 * 4);
        #pragma unroll
        for (int kk = 0; kk < 4; ++kk) {
            int c = tid + kk * 256;
            int row = c >> 4, col = c & 15;
            cpa16(dst + (u32)(row * APAD + col * 4) * 4, src + c);
        }
        CP_COMMIT();
    }

    float vnew[2][4];
    for (int h = 0; h < NHEADS; ++h) {
        if (h == NHEADS - 1) { CP_WAIT(0); } else { CP_WAIT(1); }
        __syncthreads();               // AV(h-1) done everywhere + probs(h) visible

        if (h > 0) {                   // deferred v-update
            #pragma unroll
            for (int i = 0; i < 2; ++i)
                #pragma unroll
                for (int j = 0; j < 4; ++j)
                    s_v[(ad0 + i) * 64 + ln + 16 * j] = vnew[i][j];
        }
        __syncwarp();                  // row writers/readers share the warp

        const float* s_attn = bufs + (h & 1) * 4352;

        float pll[2][4];
        if (h < NHEADS - 1) {
            const float* src = g_llw + wbase + (size_t)(h + 1) * HD * NPOS;
            #pragma unroll
            for (int i = 0; i < 2; ++i)
                #pragma unroll
                for (int j = 0; j < 4; ++j)
                    pll[i][j] = __ldg(&src[(ad0 + i) * 64 + ln + 16 * j]);
        }

        ull acc2[2][4];
        #pragma unroll
        for (int i = 0; i < 2; ++i)
            #pragma unroll
            for (int j = 0; j < 4; ++j) acc2[i][j] = 0ULL;
        #pragma unroll 4
        for (int mq = 0; mq < 16; ++mq) {
            ulonglong2 vv0 = *(const ulonglong2*)&s_v[ad0 * 64 + mq * 4];
            ulonglong2 vv1 = *(const ulonglong2*)&s_v[(ad0 + 1) * 64 + mq * 4];
            ulonglong2 aa[4];
            #pragma unroll
            for (int j = 0; j < 4; ++j)
                aa[j] = *(const ulonglong2*)&s_attn[(ln + 16 * j) * APAD + mq * 4];
            #pragma unroll
            for (int j = 0; j < 4; ++j) {
                fma2(acc2[0][j], vv0.x, aa[j].x); fma2(acc2[0][j], vv0.y, aa[j].y);
                fma2(acc2[1][j], vv1.x, aa[j].x); fma2(acc2[1][j], vv1.y, aa[j].y);
            }
        }
        {
            size_t ob = wbase + (size_t)h * HD * NPOS;
            #pragma unroll
            for (int i = 0; i < 2; ++i) {
                int d = ad0 + i;
                #pragma unroll
                for (int j = 0; j < 4; ++j) {
                    float2 p = unpack2(acc2[i][j]);
                    float val = p.x + p.y;
                    g_relu[ob + d * 64 + ln + 16 * j] = fmaxf(val, 0.f);
                    if (h < NHEADS - 1) vnew[i][j] = val + pll[i][j];
                }
            }
        }
        __syncthreads();               // AV(h) fully done -> buf[h&1] reusable
        if (h + 2 < NHEADS) {          // prefetch probs(h+2) into buf[h&1]
            const float4* src = (const float4*)(g_attn + (size_t)(win * NHEADS + h + 2) * (NPOS * NPOS));
            u32 dst = u_buf + (u32)((h & 1) * 4352 * 4);
            #pragma unroll
            for (int kk = 0; kk < 4; ++kk) {
                int c = tid + kk * 256;
                int row = c >> 4, col = c & 15;
                cpa16(dst + (u32)(row * APAD + col * 4) * 4, src + c);
            }
            CP_COMMIT();
        }
    }
}

// ---------------------------------------------------------------------------
// Kernel B3: batched proj GEMM (unchanged, FFMA2-bound)
// ---------------------------------------------------------------------------
__global__ void __launch_bounds__(256) proj_kernel(const float* __restrict__ pw,
                                                   const float* __restrict__ pb) {
    extern __shared__ float psm[];
    float* sW  = psm;                       // [cl][o], stride 258
    ull*   sXd = (ull*)(psm + 32 * 258);    // [cl][n] duplicated pairs

    int win = blockIdx.x;
    int tid = threadIdx.x;
    int to  = (tid >> 3) << 3;
    int lnn = tid & 7;

    ull acc2[4][8];
    #pragma unroll
    for (int i = 0; i < 4; ++i)
        #pragma unroll
        for (int j = 0; j < 8; ++j) acc2[i][j] = 0ULL;

    for (int c0 = 0; c0 < CC; c0 += 32) {
        for (int i = tid; i < 256 * 32; i += 256) {
            int o = i >> 5, cl = i & 31;
            sW[cl * 258 + o] = pw[o * 256 + c0 + cl];
        }
        {
            const float* xs = g_relu + (size_t)(win * CC + c0) * NPOS;
            #pragma unroll
            for (int k = 0; k < 8; ++k) {
                int j = tid + k * 256;
                float v = xs[j];
                sXd[j] = pack2(v, v);
            }
        }
        __syncthreads();

        #pragma unroll 2
        for (int cl = 0; cl < 32; ++cl) {
            ull w2[4];
            #pragma unroll
            for (int i = 0; i < 4; ++i)
                w2[i] = *(const ull*)&sW[cl * 258 + to + 2 * i];
            ull xd[8];
            #pragma unroll
            for (int j = 0; j < 8; ++j) xd[j] = sXd[cl * 64 + lnn + 8 * j];
            #pragma unroll
            for (int i = 0; i < 4; ++i)
                #pragma unroll
                for (int j = 0; j < 8; ++j) fma2(acc2[i][j], w2[i], xd[j]);
        }
        __syncthreads();
    }

    #pragma unroll
    for (int i = 0; i < 4; ++i) {
        int o0 = to + 2 * i;
        float b0 = pb[o0], b1 = pb[o0 + 1];
        float* out0 = g_llout + (size_t)(win * CC + o0) * NPOS;
        float* out1 = out0 + NPOS;
        #pragma unroll
        for (int j = 0; j < 8; ++j) {
            float2 p = unpack2(acc2[i][j]);
            int n = lnn + 8 * j;
            out0[n] = p.x + b0;
            out1[n] = p.y + b1;
        }
    }
}

// ---------------------------------------------------------------------------
// Kernel C: inverse wavelet, 2 cells per thread
// ---------------------------------------------------------------------------
__global__ void iwt_kernel(const float* __restrict__ iwf, float* __restrict__ out) {
    int idx = blockIdx.x * blockDim.x + threadIdx.x;
    int xp = idx & 63;
    int y  = (idx >> 6) & 127;
    int ch = (idx >> 13) & 255;
    int b  = idx >> 21;
    int xx = xp << 1;

    int win = b * 256 + (y >> 3) * 16 + (xx >> 3);
    int off = (win * CC + ch) * NPOS + (y & 7) * 8 + (xx & 7);
    float2 v0 = *(const float2*)&g_llout[off];
    float2 v1 = *(const float2*)&g_lhw[off];
    float2 v2 = *(const float2*)&g_hlw[off];
    float2 v3 = *(const float2*)&g_hhw[off];

    const float* w = iwf + ch * 16;
    float* po = out + (((size_t)(b * CC + ch) * 256 + 2 * y) * 256 + 2 * xx);

    float4 r0, r1;
    r0.x = w[0]*v0.x + w[4]*v1.x + w[8]*v2.x  + w[12]*v3.x;
    r0.y = w[1]*v0.x + w[5]*v1.x + w[9]*v2.x  + w[13]*v3.x;
    r0.z = w[0]*v0.y + w[4]*v1.y + w[8]*v2.y  + w[12]*v3.y;
    r0.w = w[1]*v0.y + w[5]*v1.y + w[9]*v2.y  + w[13]*v3.y;
    r1.x = w[2]*v0.x + w[6]*v1.x + w[10]*v2.x + w[14]*v3.x;
    r1.y = w[3]*v0.x + w[7]*v1.x + w[11]*v2.x + w[15]*v3.x;
    r1.z = w[2]*v0.y + w[6]*v1.y + w[10]*v2.y + w[14]*v3.y;
    r1.w = w[3]*v0.y + w[7]*v1.y + w[11]*v2.y + w[15]*v3.y;

    *(float4*)po         = r0;
    *(float4*)(po + 256) = r1;
}

// ---------------------------------------------------------------------------
extern "C" void kernel_launch(void* const* d_in, const int* in_sizes, int n_in,
                              void* d_out, int out_size) {
    const float* x    = (const float*)d_in[0];
    const float* wtf  = (const float*)d_in[1];
    const float* iwtf = (const float*)d_in[2];
    const float* dww  = (const float*)d_in[3];
    const float* dwb  = (const float*)d_in[4];
    const float* pw   = (const float*)d_in[5];
    const float* pb   = (const float*)d_in[6];
    const float* ab   = (const float*)d_in[7];
    float* out = (float*)d_out;

    int half = BB * CC * H2 * W2 / 2;  // 4,194,304
    wt_kernel<<<half / 256, 256>>>(x, wtf);

    size_t qsmem = 7504 * sizeof(float);    // 30016 B
    cudaFuncSetAttribute(qk_kernel, cudaFuncAttributeMaxDynamicSharedMemorySize, (int)qsmem);
    qk_kernel<<<NWIN * NHEADS, 256, qsmem>>>(dww, dwb, ab);

    size_t avsmem = 10752 * sizeof(float);  // 43008 B
    cudaFuncSetAttribute(av_kernel, cudaFuncAttributeMaxDynamicSharedMemorySize, (int)avsmem);
    av_kernel<<<NWIN, 256, avsmem>>>();

    size_t psmem = (32 * 258) * sizeof(float) + 2048 * sizeof(ull);  // 49408 B
    cudaFuncSetAttribute(proj_kernel, cudaFuncAttributeMaxDynamicSharedMemorySize, (int)psmem);
    proj_kernel<<<NWIN, 256, psmem>>>(pw, pb);

    iwt_kernel<<<half / 256, 256>>>(iwtf, out);
}